// round 15
// baseline (speedup 1.0000x reference)
#include <cuda_runtime.h>
#include <cuda_fp16.h>
#include <cstdint>
#include <math.h>

#define B 1024
#define NNE 100000
#define NPAD2 100224         // padded rows of E: 348 * 288
#define D 200
#define KP 208               // K padded: 6 chunks of 32 + 1 chunk of 16
#define OC 32
#define FW 9
#define LL 192               // D - FW + 1
#define KTOT (OC * LL)       // 6144
#define KFW (OC * FW)        // 288
#define KSPLIT 8
#define NPW 256              // padded output cols of kC1m
#define EPSV 1e-5f

// kD tiling: 256 mma cols + 32 FFMA cols per block
#define BM 64
#define BN 256
#define BNF 288
#define NK 7                 // 6 full chunks (32) + 1 tail chunk (16)
#define NSTG 3
#define KD_SMEM (NSTG * (BM + BNF) * 40 * 2)   // 84480 B

// kC1m tiling
#define C_BM 64
#define C_BN 128
#define C_STEPS (KTOT / KSPLIT / 16)   // 48

// scratch (no allocations allowed)
__device__ __half g_yb[B * KTOT];
__device__ __half g_Wb[(size_t)NPW * KTOT];
__device__ float g_hp[(size_t)KSPLIT * B * NPW];
__device__ __half g_hb[B * KP];
__device__ __half g_Eb[(size_t)NPAD2 * KP];

// ---------------------------------------------------------------------------
// convE: E (fp32, NNE x D) -> g_Eb (fp16, NPAD2 x KP) zero-padded
// ---------------------------------------------------------------------------
__global__ void convE(const float* __restrict__ E) {
    size_t i = (size_t)blockIdx.x * blockDim.x + threadIdx.x;
    if (i >= (size_t)NPAD2 * KP) return;
    int n = (int)(i / KP);
    int k = (int)(i % KP);
    float v = (n < NNE && k < D) ? E[(size_t)n * D + k] : 0.f;
    g_Eb[i] = __float2half(v);
}

// ---------------------------------------------------------------------------
// convW: W_fc (fp32, KTOT x D) -> g_Wb (fp16, NPW x KTOT) transposed, padded
// ---------------------------------------------------------------------------
__global__ void convW(const float* __restrict__ W_fc) {
    size_t i = (size_t)blockIdx.x * blockDim.x + threadIdx.x;
    if (i >= (size_t)NPW * KTOT) return;
    int k = (int)(i / NPW);
    int n = (int)(i % NPW);
    float v = (n < D) ? W_fc[(size_t)k * D + n] : 0.f;
    g_Wb[(size_t)n * KTOT + k] = __float2half(v);
}

// ---------------------------------------------------------------------------
// kAB (fused, batched x8)
// ---------------------------------------------------------------------------
__global__ void kAB(const int* __restrict__ e1_idx, const int* __restrict__ r_idx,
                    const float* __restrict__ E, const float* __restrict__ R,
                    const float* __restrict__ W_fc1, const float* __restrict__ b_fc1,
                    const float* __restrict__ pg0, const float* __restrict__ pb0,
                    const float* __restrict__ pm0, const float* __restrict__ pv0,
                    const float* __restrict__ g1, const float* __restrict__ b1,
                    const float* __restrict__ m1, const float* __restrict__ v1) {
    int bbase = blockIdx.x * 8;
    int t = threadIdx.x;
    __shared__ float rs[8][D];
    __shared__ float xs[8][D];
    __shared__ float kb[8][KFW];
    float s0 = pg0[0] / sqrtf(pv0[0] + EPSV);
    float bb0 = pb0[0], mm0 = pm0[0];
    for (int i = t; i < 8 * D; i += KFW) {
        int g = i / D, d = i % D;
        int bi = bbase + g;
        rs[g][d] = R[(size_t)r_idx[bi] * D + d];
        xs[g][d] = (E[(size_t)e1_idx[bi] * D + d] - mm0) * s0 + bb0;
    }
    __syncthreads();
    {
        float acc[8];
#pragma unroll
        for (int g = 0; g < 8; g++) acc[g] = b_fc1[t];
        for (int d = 0; d < D; d++) {
            float w = W_fc1[d * KFW + t];
#pragma unroll
            for (int g = 0; g < 8; g++) acc[g] += rs[g][d] * w;
        }
#pragma unroll
        for (int g = 0; g < 8; g++) kb[g][t] = acc[g];
    }
    __syncthreads();
    if (t < LL) {
        int l = t;
        for (int o = 0; o < OC; o++) {
            float s = g1[o] / sqrtf(v1[o] + EPSV);
            float mo = m1[o], bo = b1[o];
#pragma unroll
            for (int g = 0; g < 8; g++) {
                float acc = 0.f;
#pragma unroll
                for (int w = 0; w < FW; w++) acc += xs[g][l + w] * kb[g][o * FW + w];
                g_yb[(bbase + g) * KTOT + o * LL + l] = __float2half((acc - mo) * s + bo);
            }
        }
    }
}

// ---------------------------------------------------------------------------
// Kernel C1m: partial h = Y @ Wb^T, split-K=8 (round-11 version)
// ---------------------------------------------------------------------------
__global__ void __launch_bounds__(256)
kC1m() {
    __shared__ __align__(16) __half As[NSTG][C_BM][24];
    __shared__ __align__(16) __half Bs[NSTG][C_BN][24];

    const int m0 = blockIdx.x * C_BM;
    const int n0 = blockIdx.y * C_BN;
    const int ks = blockIdx.z;
    const int k0 = ks * (KTOT / KSPLIT);
    const int tid = threadIdx.x;
    const int lane = tid & 31;
    const int wid = tid >> 5;
    const int wm = wid >> 2;
    const int wn = wid & 3;

    float acc[2][4][4];
#pragma unroll
    for (int i = 0; i < 2; i++)
#pragma unroll
        for (int j = 0; j < 4; j++)
#pragma unroll
            for (int c = 0; c < 4; c++) acc[i][j][c] = 0.f;

    const int arow = tid >> 1, ac8 = (tid & 1) * 8;

#define LOAD_C(S, KS)                                                            \
    do {                                                                         \
        if (tid < 128) {                                                         \
            unsigned dst = (unsigned)__cvta_generic_to_shared(&As[S][arow][ac8]);\
            const __half* src = &g_yb[(size_t)(m0 + arow) * KTOT + k0 + (KS) + ac8];\
            asm volatile("cp.async.cg.shared.global [%0], [%1], 16;\n"           \
                         :: "r"(dst), "l"(src));                                 \
        }                                                                        \
        {                                                                        \
            unsigned dst = (unsigned)__cvta_generic_to_shared(&Bs[S][arow][ac8]);\
            const __half* src = &g_Wb[(size_t)(n0 + arow) * KTOT + k0 + (KS) + ac8];\
            asm volatile("cp.async.cg.shared.global [%0], [%1], 16;\n"           \
                         :: "r"(dst), "l"(src));                                 \
        }                                                                        \
        asm volatile("cp.async.commit_group;\n" ::);                             \
    } while (0)

    LOAD_C(0, 0);
    LOAD_C(1, 16);

    int st = 0;
    int stp = 2;
    for (int s = 0; s < C_STEPS; s++) {
        asm volatile("cp.async.wait_group 1;\n" ::);
        __syncthreads();

        if (s + 2 < C_STEPS) {
            LOAD_C(stp, (s + 2) * 16);
        } else {
            asm volatile("cp.async.commit_group;\n" ::);
        }

        unsigned a[2][4];
        unsigned bfr[4][2];
#pragma unroll
        for (int mi = 0; mi < 2; mi++) {
            unsigned addr = (unsigned)__cvta_generic_to_shared(
                &As[st][wm * 32 + mi * 16 + (lane & 15)][(lane >> 4) * 8]);
            asm volatile("ldmatrix.sync.aligned.m8n8.x4.shared.b16 {%0,%1,%2,%3}, [%4];"
                         : "=r"(a[mi][0]), "=r"(a[mi][1]), "=r"(a[mi][2]), "=r"(a[mi][3])
                         : "r"(addr));
        }
#pragma unroll
        for (int p = 0; p < 2; p++) {
            unsigned addr = (unsigned)__cvta_generic_to_shared(
                &Bs[st][wn * 32 + p * 16 + ((lane >> 4) << 3) + (lane & 7)]
                   [((lane >> 3) & 1) * 8]);
            asm volatile("ldmatrix.sync.aligned.m8n8.x4.shared.b16 {%0,%1,%2,%3}, [%4];"
                         : "=r"(bfr[2 * p][0]), "=r"(bfr[2 * p][1]),
                           "=r"(bfr[2 * p + 1][0]), "=r"(bfr[2 * p + 1][1])
                         : "r"(addr));
        }
#pragma unroll
        for (int mi = 0; mi < 2; mi++)
#pragma unroll
            for (int ni = 0; ni < 4; ni++) {
                asm volatile(
                    "mma.sync.aligned.m16n8k16.row.col.f32.f16.f16.f32 "
                    "{%0,%1,%2,%3}, {%4,%5,%6,%7}, {%8,%9}, {%0,%1,%2,%3};"
                    : "+f"(acc[mi][ni][0]), "+f"(acc[mi][ni][1]),
                      "+f"(acc[mi][ni][2]), "+f"(acc[mi][ni][3])
                    : "r"(a[mi][0]), "r"(a[mi][1]), "r"(a[mi][2]), "r"(a[mi][3]),
                      "r"(bfr[ni][0]), "r"(bfr[ni][1]));
            }
        st = (st == NSTG - 1) ? 0 : st + 1;
        stp = (stp == NSTG - 1) ? 0 : stp + 1;
    }

    const int rin = lane >> 2;
    const int cin = (lane & 3) * 2;
    float* hp = g_hp + (size_t)ks * B * NPW;
#pragma unroll
    for (int mi = 0; mi < 2; mi++) {
#pragma unroll
        for (int ni = 0; ni < 4; ni++) {
            int m = m0 + wm * 32 + mi * 16 + rin;
            int n = n0 + wn * 32 + ni * 8 + cin;
            float2 v0 = make_float2(acc[mi][ni][0], acc[mi][ni][1]);
            float2 v1 = make_float2(acc[mi][ni][2], acc[mi][ni][3]);
            *(float2*)(hp + (size_t)m * NPW + n)       = v0;
            *(float2*)(hp + (size_t)(m + 8) * NPW + n) = v1;
        }
    }
#undef LOAD_C
}

// ---------------------------------------------------------------------------
// Kernel C2: reduce split-K, + b_fc, bn2, relu -> g_hb (fp16, K padded)
// ---------------------------------------------------------------------------
__global__ void kC2(const float* __restrict__ b_fc,
                    const float* __restrict__ g2, const float* __restrict__ b2,
                    const float* __restrict__ m2, const float* __restrict__ v2) {
    int i = blockIdx.x * blockDim.x + threadIdx.x;
    if (i >= B * KP) return;
    int b = i / KP;
    int d = i % KP;
    if (d >= D) { g_hb[i] = __float2half(0.f); return; }
    float s = 0.f;
#pragma unroll
    for (int ks = 0; ks < KSPLIT; ks++)
        s += g_hp[(size_t)ks * B * NPW + (size_t)b * NPW + d];
    s += b_fc[d];
    float sc = g2[d] / sqrtf(v2[d] + EPSV);
    s = (s - m2[d]) * sc + b2[d];
    g_hb[i] = __float2half(fmaxf(s, 0.f));
}

// ---------------------------------------------------------------------------
// Kernel D: out[m,n] = sigmoid( h[m,:] . E[n,:] + bias[n] )
// Dual-pipe: cols [0,256) via fp16 mma (f32 acc, k8 tail), cols [256,288)
// via HFMA2 on the fma pipe in the HMMA shadow (fp16 chunk partials,
// fp32 masters). Block covers 64 x 288. grid = (B/BM, NPAD2/BNF).
// ---------------------------------------------------------------------------
__global__ void __launch_bounds__(256, 2)
kD(const float* __restrict__ bias, float* __restrict__ out) {
    extern __shared__ __align__(16) __half dsm[];
    __half* Asm = dsm;                        // [NSTG][BM][40]
    __half* Bsm = dsm + NSTG * BM * 40;       // [NSTG][BNF][40]

    const int m0 = blockIdx.x * BM;
    const int n0 = blockIdx.y * BNF;
    const int tid = threadIdx.x;
    const int lane = tid & 31;
    const int wid = tid >> 5;
    const int wm = wid >> 2;    // 0..1  -> m offset 32
    const int wn = wid & 3;     // 0..3  -> n offset 64

    // FFMA side mapping: 1 row x 8 cols per thread
    const int rr = tid & 63;               // m row
    const int cc = (tid >> 6) * 8;         // col base within [0,32)

    float acc[2][8][4];
#pragma unroll
    for (int i = 0; i < 2; i++)
#pragma unroll
        for (int j = 0; j < 8; j++)
#pragma unroll
            for (int c = 0; c < 4; c++) acc[i][j][c] = 0.f;

    float fm[8];
#pragma unroll
    for (int j = 0; j < 8; j++) fm[j] = 0.f;

#define LOAD_D32(S, KS)                                                            \
    do {                                                                           \
        {   int r = tid >> 2, c8 = (tid & 3) * 8;                                  \
            unsigned dst = (unsigned)__cvta_generic_to_shared(                     \
                &Asm[((S) * BM + r) * 40 + c8]);                                   \
            const __half* src = &g_hb[(size_t)(m0 + r) * KP + (KS) + c8];          \
            asm volatile("cp.async.cg.shared.global [%0], [%1], 16;\n"             \
                         :: "r"(dst), "l"(src)); }                                 \
        _Pragma("unroll")                                                          \
        for (int h = 0; h < 5; h++) {                                              \
            int idx = tid + h * 256;                                               \
            if (idx < BNF * 4) {                                                   \
                int r = idx >> 2, c8 = (idx & 3) * 8;                              \
                unsigned dst = (unsigned)__cvta_generic_to_shared(                 \
                    &Bsm[((S) * BNF + r) * 40 + c8]);                              \
                const __half* src = &g_Eb[(size_t)(n0 + r) * KP + (KS) + c8];      \
                asm volatile("cp.async.cg.shared.global [%0], [%1], 16;\n"         \
                             :: "r"(dst), "l"(src));                               \
            }                                                                      \
        }                                                                          \
        asm volatile("cp.async.commit_group;\n" ::);                               \
    } while (0)

#define LOAD_D16(S, KS)                                                            \
    do {                                                                           \
        if (tid < 128) {                                                           \
            int r = tid >> 1, c8 = (tid & 1) * 8;                                  \
            unsigned dst = (unsigned)__cvta_generic_to_shared(                     \
                &Asm[((S) * BM + r) * 40 + c8]);                                   \
            const __half* src = &g_hb[(size_t)(m0 + r) * KP + (KS) + c8];          \
            asm volatile("cp.async.cg.shared.global [%0], [%1], 16;\n"             \
                         :: "r"(dst), "l"(src)); }                                 \
        _Pragma("unroll")                                                          \
        for (int h = 0; h < 3; h++) {                                              \
            int idx = tid + h * 256;                                               \
            if (idx < BNF * 2) {                                                   \
                int r = idx >> 1, c8 = (idx & 1) * 8;                              \
                unsigned dst = (unsigned)__cvta_generic_to_shared(                 \
                    &Bsm[((S) * BNF + r) * 40 + c8]);                              \
                const __half* src = &g_Eb[(size_t)(n0 + r) * KP + (KS) + c8];      \
                asm volatile("cp.async.cg.shared.global [%0], [%1], 16;\n"         \
                             :: "r"(dst), "l"(src));                               \
            }                                                                      \
        }                                                                          \
        asm volatile("cp.async.commit_group;\n" ::);                               \
    } while (0)

// FFMA side computation for one chunk (KQ uint4 = KQ*8 halves of K)
#define FFMA_SIDE(ST, KQ)                                                          \
    do {                                                                           \
        const uint4* arow = (const uint4*)(Asm + ((ST) * BM + rr) * 40);           \
        uint4 av[4];                                                               \
        _Pragma("unroll")                                                          \
        for (int q = 0; q < (KQ); q++) av[q] = arow[q];                            \
        _Pragma("unroll")                                                          \
        for (int j = 0; j < 8; j++) {                                              \
            const uint4* brow = (const uint4*)(Bsm + ((ST) * BNF + 256 + cc + j) * 40);\
            __half2 s2 = __floats2half2_rn(0.f, 0.f);                              \
            _Pragma("unroll")                                                      \
            for (int q = 0; q < (KQ); q++) {                                       \
                uint4 bv = brow[q];                                                \
                const __half2* ah = (const __half2*)&av[q];                        \
                const __half2* bh = (const __half2*)&bv;                           \
                s2 = __hfma2(ah[0], bh[0], s2);                                    \
                s2 = __hfma2(ah[1], bh[1], s2);                                    \
                s2 = __hfma2(ah[2], bh[2], s2);                                    \
                s2 = __hfma2(ah[3], bh[3], s2);                                    \
            }                                                                      \
            float2 f = __half22float2(s2);                                         \
            fm[j] += f.x + f.y;                                                    \
        }                                                                          \
    } while (0)

    LOAD_D32(0, 0);
    LOAD_D32(1, 32);

    int st = 0;
    int stp = 2;
#pragma unroll
    for (int s = 0; s < NK; s++) {
        asm volatile("cp.async.wait_group 1;\n" ::);
        __syncthreads();

        if (s + 2 < NK) {
            if (s + 2 == NK - 1) { LOAD_D16(stp, (s + 2) * 32); }
            else                 { LOAD_D32(stp, (s + 2) * 32); }
        } else {
            asm volatile("cp.async.commit_group;\n" ::);
        }

        if (s < NK - 1) {
            // full chunk: two k16 ksubs on mma cols [0,256)
#pragma unroll
            for (int ksub = 0; ksub < 2; ksub++) {
                unsigned a[2][4];
                unsigned bfr[8][2];
#pragma unroll
                for (int mi = 0; mi < 2; mi++) {
                    unsigned addr = (unsigned)__cvta_generic_to_shared(
                        &Asm[(st * BM + wm * 32 + mi * 16 + (lane & 15)) * 40
                             + ksub * 16 + (lane >> 4) * 8]);
                    asm volatile("ldmatrix.sync.aligned.m8n8.x4.shared.b16 {%0,%1,%2,%3}, [%4];"
                                 : "=r"(a[mi][0]), "=r"(a[mi][1]), "=r"(a[mi][2]), "=r"(a[mi][3])
                                 : "r"(addr));
                }
#pragma unroll
                for (int p = 0; p < 4; p++) {
                    unsigned addr = (unsigned)__cvta_generic_to_shared(
                        &Bsm[(st * BNF + wn * 64 + p * 16 + ((lane >> 4) << 3) + (lane & 7)) * 40
                             + ksub * 16 + ((lane >> 3) & 1) * 8]);
                    asm volatile("ldmatrix.sync.aligned.m8n8.x4.shared.b16 {%0,%1,%2,%3}, [%4];"
                                 : "=r"(bfr[2 * p][0]), "=r"(bfr[2 * p][1]),
                                   "=r"(bfr[2 * p + 1][0]), "=r"(bfr[2 * p + 1][1])
                                 : "r"(addr));
                }
#pragma unroll
                for (int mi = 0; mi < 2; mi++)
#pragma unroll
                    for (int ni = 0; ni < 8; ni++) {
                        asm volatile(
                            "mma.sync.aligned.m16n8k16.row.col.f32.f16.f16.f32 "
                            "{%0,%1,%2,%3}, {%4,%5,%6,%7}, {%8,%9}, {%0,%1,%2,%3};"
                            : "+f"(acc[mi][ni][0]), "+f"(acc[mi][ni][1]),
                              "+f"(acc[mi][ni][2]), "+f"(acc[mi][ni][3])
                            : "r"(a[mi][0]), "r"(a[mi][1]), "r"(a[mi][2]), "r"(a[mi][3]),
                              "r"(bfr[ni][0]), "r"(bfr[ni][1]));
                    }
            }
            FFMA_SIDE(st, 4);
        } else {
            // tail chunk: k = 192..200 real; single m16n8k8 on fragment halves.
            unsigned a[2][4];
            unsigned bfr[8][2];
#pragma unroll
            for (int mi = 0; mi < 2; mi++) {
                unsigned addr = (unsigned)__cvta_generic_to_shared(
                    &Asm[(st * BM + wm * 32 + mi * 16 + (lane & 15)) * 40
                         + (lane >> 4) * 8]);
                asm volatile("ldmatrix.sync.aligned.m8n8.x4.shared.b16 {%0,%1,%2,%3}, [%4];"
                             : "=r"(a[mi][0]), "=r"(a[mi][1]), "=r"(a[mi][2]), "=r"(a[mi][3])
                             : "r"(addr));
            }
#pragma unroll
            for (int p = 0; p < 4; p++) {
                unsigned addr = (unsigned)__cvta_generic_to_shared(
                    &Bsm[(st * BNF + wn * 64 + p * 16 + ((lane >> 4) << 3) + (lane & 7)) * 40
                         + ((lane >> 3) & 1) * 8]);
                asm volatile("ldmatrix.sync.aligned.m8n8.x4.shared.b16 {%0,%1,%2,%3}, [%4];"
                             : "=r"(bfr[2 * p][0]), "=r"(bfr[2 * p][1]),
                               "=r"(bfr[2 * p + 1][0]), "=r"(bfr[2 * p + 1][1])
                             : "r"(addr));
            }
#pragma unroll
            for (int mi = 0; mi < 2; mi++)
#pragma unroll
                for (int ni = 0; ni < 8; ni++) {
                    asm volatile(
                        "mma.sync.aligned.m16n8k8.row.col.f32.f16.f16.f32 "
                        "{%0,%1,%2,%3}, {%4,%5}, {%6}, {%0,%1,%2,%3};"
                        : "+f"(acc[mi][ni][0]), "+f"(acc[mi][ni][1]),
                          "+f"(acc[mi][ni][2]), "+f"(acc[mi][ni][3])
                        : "r"(a[mi][0]), "r"(a[mi][1]),
                          "r"(bfr[ni][0]));
                }
            FFMA_SIDE(st, 2);   // 16 halves incl. zero pad (k 200..207)
        }
        st = (st == NSTG - 1) ? 0 : st + 1;
        stp = (stp == NSTG - 1) ? 0 : stp + 1;
    }

    // mma epilogue: bias + sigmoid (fast reciprocal), float2 stores
    const int rin = lane >> 2;
    const int cin = (lane & 3) * 2;
#pragma unroll
    for (int ni = 0; ni < 8; ni++) {
        int n = n0 + wn * 64 + ni * 8 + cin;
        if (n >= NNE) continue;
        float2 bz = *(const float2*)(bias + n);
#pragma unroll
        for (int mi = 0; mi < 2; mi++) {
            int m = m0 + wm * 32 + mi * 16 + rin;
            float2 o0, o1;
            o0.x = __fdividef(1.f, 1.f + __expf(-(acc[mi][ni][0] + bz.x)));
            o0.y = __fdividef(1.f, 1.f + __expf(-(acc[mi][ni][1] + bz.y)));
            o1.x = __fdividef(1.f, 1.f + __expf(-(acc[mi][ni][2] + bz.x)));
            o1.y = __fdividef(1.f, 1.f + __expf(-(acc[mi][ni][3] + bz.y)));
            *(float2*)(out + (size_t)m * NNE + n)       = o0;
            *(float2*)(out + (size_t)(m + 8) * NNE + n) = o1;
        }
    }

    // FFMA epilogue: cols [n0+256, n0+288)
    {
        int m = m0 + rr;
        int nb = n0 + 256 + cc;
        if (nb < NNE) {   // NNE % 8 == 0 -> all-or-nothing per 8 cols
            float4 bz0 = *(const float4*)(bias + nb);
            float4 bz1 = *(const float4*)(bias + nb + 4);
            float4 o0, o1;
            o0.x = __fdividef(1.f, 1.f + __expf(-(fm[0] + bz0.x)));
            o0.y = __fdividef(1.f, 1.f + __expf(-(fm[1] + bz0.y)));
            o0.z = __fdividef(1.f, 1.f + __expf(-(fm[2] + bz0.z)));
            o0.w = __fdividef(1.f, 1.f + __expf(-(fm[3] + bz0.w)));
            o1.x = __fdividef(1.f, 1.f + __expf(-(fm[4] + bz1.x)));
            o1.y = __fdividef(1.f, 1.f + __expf(-(fm[5] + bz1.y)));
            o1.z = __fdividef(1.f, 1.f + __expf(-(fm[6] + bz1.z)));
            o1.w = __fdividef(1.f, 1.f + __expf(-(fm[7] + bz1.w)));
            *(float4*)(out + (size_t)m * NNE + nb)     = o0;
            *(float4*)(out + (size_t)m * NNE + nb + 4) = o1;
        }
    }
#undef LOAD_D32
#undef LOAD_D16
#undef FFMA_SIDE
}

// ---------------------------------------------------------------------------
extern "C" void kernel_launch(void* const* d_in, const int* in_sizes, int n_in,
                              void* d_out, int out_size) {
    const int*   e1_idx = (const int*)d_in[0];
    const int*   r_idx  = (const int*)d_in[1];
    const float* E      = (const float*)d_in[2];
    const float* R      = (const float*)d_in[3];
    const float* W_fc   = (const float*)d_in[4];
    const float* b_fc   = (const float*)d_in[5];
    const float* W_fc1  = (const float*)d_in[6];
    const float* b_fc1  = (const float*)d_in[7];
    const float* bn0_g  = (const float*)d_in[8];
    const float* bn0_b  = (const float*)d_in[9];
    const float* bn0_m  = (const float*)d_in[10];
    const float* bn0_v  = (const float*)d_in[11];
    const float* bn1_g  = (const float*)d_in[12];
    const float* bn1_b  = (const float*)d_in[13];
    const float* bn1_m  = (const float*)d_in[14];
    const float* bn1_v  = (const float*)d_in[15];
    const float* bn2_g  = (const float*)d_in[16];
    const float* bn2_b  = (const float*)d_in[17];
    const float* bn2_m  = (const float*)d_in[18];
    const float* bn2_v  = (const float*)d_in[19];
    const float* bvec   = (const float*)d_in[20];
    float* out = (float*)d_out;

    static int init_done = 0;
    static cudaStream_t s1;
    static cudaEvent_t evFork, evW, evE;
    if (!init_done) {
        cudaFuncSetAttribute(kD, cudaFuncAttributeMaxDynamicSharedMemorySize, KD_SMEM);
        cudaStreamCreateWithFlags(&s1, cudaStreamNonBlocking);
        cudaEventCreateWithFlags(&evFork, cudaEventDisableTiming);
        cudaEventCreateWithFlags(&evW, cudaEventDisableTiming);
        cudaEventCreateWithFlags(&evE, cudaEventDisableTiming);
        init_done = 1;
    }

    // DAG (round-11/14 best):
    //   s0: kAB ---(wait evW)--> kC1m -> kC2 --(wait evE)--> kD
    //   s1: convW -evW-> convE -evE
    cudaEventRecord(evFork, 0);
    cudaStreamWaitEvent(s1, evFork, 0);
    convW<<<(int)(((size_t)NPW * KTOT + 255) / 256), 256, 0, s1>>>(W_fc);
    cudaEventRecord(evW, s1);
    convE<<<(int)(((size_t)NPAD2 * KP + 255) / 256), 256, 0, s1>>>(E);
    cudaEventRecord(evE, s1);

    kAB<<<B / 8, KFW>>>(e1_idx, r_idx, E, R, W_fc1, b_fc1,
                        bn0_g, bn0_b, bn0_m, bn0_v, bn1_g, bn1_b, bn1_m, bn1_v);
    cudaStreamWaitEvent(0, evW, 0);
    kC1m<<<dim3(B / C_BM, NPW / C_BN, KSPLIT), 256>>>();
    kC2<<<(B * KP + 255) / 256, 256>>>(b_fc, bn2_g, bn2_b, bn2_m, bn2_v);

    cudaStreamWaitEvent(0, evE, 0);
    dim3 gD(B / BM, NPAD2 / BNF);
    kD<<<gD, 256, KD_SMEM>>>(bvec, out);
}

// round 16
// speedup vs baseline: 1.3131x; 1.3131x over previous
#include <cuda_runtime.h>
#include <cuda_fp16.h>
#include <cstdint>
#include <math.h>

#define B 1024
#define NNE 100000
#define NPAD 100096          // padded rows of E (multiple of 256)
#define D 200
#define KP 208               // K padded: 6 chunks of 32 + 1 chunk of 16
#define OC 32
#define FW 9
#define LL 192               // D - FW + 1
#define KTOT (OC * LL)       // 6144
#define KFW (OC * FW)        // 288
#define KSPLIT 8
#define NPW 256              // padded output cols of kC1m
#define EPSV 1e-5f

// kD tiling
#define BM 64
#define BN 256
#define NK 7                 // 6 full chunks (32) + 1 tail chunk (16)
#define NSTG 3
#define KD_SMEM (NSTG * (BM + BN) * 40 * 2)   // 76800 B

// kC1m tiling
#define C_BM 64
#define C_BN 128
#define C_STEPS (KTOT / KSPLIT / 16)   // 48

// scratch (no allocations allowed)
__device__ __half g_yb[B * KTOT];
__device__ __half g_Wb[(size_t)NPW * KTOT];
__device__ float g_hp[(size_t)KSPLIT * B * NPW];
__device__ __half g_hb[B * KP];
__device__ __half g_Eb[(size_t)NPAD * KP];

// ---------------------------------------------------------------------------
// convE: E (fp32, NNE x D) -> g_Eb (fp16, NPAD x KP) zero-padded
// ---------------------------------------------------------------------------
__global__ void convE(const float* __restrict__ E) {
    size_t i = (size_t)blockIdx.x * blockDim.x + threadIdx.x;
    if (i >= (size_t)NPAD * KP) return;
    int n = (int)(i / KP);
    int k = (int)(i % KP);
    float v = (n < NNE && k < D) ? E[(size_t)n * D + k] : 0.f;
    g_Eb[i] = __float2half(v);
}

// ---------------------------------------------------------------------------
// convW: W_fc (fp32, KTOT x D) -> g_Wb (fp16, NPW x KTOT) transposed, padded
// ---------------------------------------------------------------------------
__global__ void convW(const float* __restrict__ W_fc) {
    size_t i = (size_t)blockIdx.x * blockDim.x + threadIdx.x;
    if (i >= (size_t)NPW * KTOT) return;
    int k = (int)(i / NPW);
    int n = (int)(i % NPW);
    float v = (n < D) ? W_fc[(size_t)k * D + n] : 0.f;
    g_Wb[(size_t)n * KTOT + k] = __float2half(v);
}

// ---------------------------------------------------------------------------
// kAB (fused, batched x8): x = bn0(E[e1]); k = R[r] @ W_fc1 + b_fc1;
//   y[b,o,l] = bn1(sum_w x[b,l+w]*k[b,o,w]) -> g_yb (fp16)
// grid = B/8, block = 288
// ---------------------------------------------------------------------------
__global__ void kAB(const int* __restrict__ e1_idx, const int* __restrict__ r_idx,
                    const float* __restrict__ E, const float* __restrict__ R,
                    const float* __restrict__ W_fc1, const float* __restrict__ b_fc1,
                    const float* __restrict__ pg0, const float* __restrict__ pb0,
                    const float* __restrict__ pm0, const float* __restrict__ pv0,
                    const float* __restrict__ g1, const float* __restrict__ b1,
                    const float* __restrict__ m1, const float* __restrict__ v1) {
    int bbase = blockIdx.x * 8;
    int t = threadIdx.x;
    __shared__ float rs[8][D];
    __shared__ float xs[8][D];
    __shared__ float kb[8][KFW];
    float s0 = pg0[0] / sqrtf(pv0[0] + EPSV);
    float bb0 = pb0[0], mm0 = pm0[0];
    for (int i = t; i < 8 * D; i += KFW) {
        int g = i / D, d = i % D;
        int bi = bbase + g;
        rs[g][d] = R[(size_t)r_idx[bi] * D + d];
        xs[g][d] = (E[(size_t)e1_idx[bi] * D + d] - mm0) * s0 + bb0;
    }
    __syncthreads();
    {
        float acc[8];
#pragma unroll
        for (int g = 0; g < 8; g++) acc[g] = b_fc1[t];
        for (int d = 0; d < D; d++) {
            float w = W_fc1[d * KFW + t];
#pragma unroll
            for (int g = 0; g < 8; g++) acc[g] += rs[g][d] * w;
        }
#pragma unroll
        for (int g = 0; g < 8; g++) kb[g][t] = acc[g];
    }
    __syncthreads();
    if (t < LL) {
        int l = t;
        for (int o = 0; o < OC; o++) {
            float s = g1[o] / sqrtf(v1[o] + EPSV);
            float mo = m1[o], bo = b1[o];
#pragma unroll
            for (int g = 0; g < 8; g++) {
                float acc = 0.f;
#pragma unroll
                for (int w = 0; w < FW; w++) acc += xs[g][l + w] * kb[g][o * FW + w];
                g_yb[(bbase + g) * KTOT + o * LL + l] = __float2half((acc - mo) * s + bo);
            }
        }
    }
}

// ---------------------------------------------------------------------------
// Kernel C1m: partial h = Y(1024x6144,fp16) @ Wb^T (NPWx6144,fp16), split-K=8
// ---------------------------------------------------------------------------
__global__ void __launch_bounds__(256)
kC1m() {
    __shared__ __align__(16) __half As[NSTG][C_BM][24];
    __shared__ __align__(16) __half Bs[NSTG][C_BN][24];

    const int m0 = blockIdx.x * C_BM;
    const int n0 = blockIdx.y * C_BN;
    const int ks = blockIdx.z;
    const int k0 = ks * (KTOT / KSPLIT);
    const int tid = threadIdx.x;
    const int lane = tid & 31;
    const int wid = tid >> 5;
    const int wm = wid >> 2;
    const int wn = wid & 3;

    float acc[2][4][4];
#pragma unroll
    for (int i = 0; i < 2; i++)
#pragma unroll
        for (int j = 0; j < 4; j++)
#pragma unroll
            for (int c = 0; c < 4; c++) acc[i][j][c] = 0.f;

    const int arow = tid >> 1, ac8 = (tid & 1) * 8;

#define LOAD_C(S, KS)                                                            \
    do {                                                                         \
        if (tid < 128) {                                                         \
            unsigned dst = (unsigned)__cvta_generic_to_shared(&As[S][arow][ac8]);\
            const __half* src = &g_yb[(size_t)(m0 + arow) * KTOT + k0 + (KS) + ac8];\
            asm volatile("cp.async.cg.shared.global [%0], [%1], 16;\n"           \
                         :: "r"(dst), "l"(src));                                 \
        }                                                                        \
        {                                                                        \
            unsigned dst = (unsigned)__cvta_generic_to_shared(&Bs[S][arow][ac8]);\
            const __half* src = &g_Wb[(size_t)(n0 + arow) * KTOT + k0 + (KS) + ac8];\
            asm volatile("cp.async.cg.shared.global [%0], [%1], 16;\n"           \
                         :: "r"(dst), "l"(src));                                 \
        }                                                                        \
        asm volatile("cp.async.commit_group;\n" ::);                             \
    } while (0)

    LOAD_C(0, 0);
    LOAD_C(1, 16);

    int st = 0;
    int stp = 2;
    for (int s = 0; s < C_STEPS; s++) {
        asm volatile("cp.async.wait_group 1;\n" ::);
        __syncthreads();

        if (s + 2 < C_STEPS) {
            LOAD_C(stp, (s + 2) * 16);
        } else {
            asm volatile("cp.async.commit_group;\n" ::);
        }

        unsigned a[2][4];
        unsigned bfr[4][2];
#pragma unroll
        for (int mi = 0; mi < 2; mi++) {
            unsigned addr = (unsigned)__cvta_generic_to_shared(
                &As[st][wm * 32 + mi * 16 + (lane & 15)][(lane >> 4) * 8]);
            asm volatile("ldmatrix.sync.aligned.m8n8.x4.shared.b16 {%0,%1,%2,%3}, [%4];"
                         : "=r"(a[mi][0]), "=r"(a[mi][1]), "=r"(a[mi][2]), "=r"(a[mi][3])
                         : "r"(addr));
        }
#pragma unroll
        for (int p = 0; p < 2; p++) {
            unsigned addr = (unsigned)__cvta_generic_to_shared(
                &Bs[st][wn * 32 + p * 16 + ((lane >> 4) << 3) + (lane & 7)]
                   [((lane >> 3) & 1) * 8]);
            asm volatile("ldmatrix.sync.aligned.m8n8.x4.shared.b16 {%0,%1,%2,%3}, [%4];"
                         : "=r"(bfr[2 * p][0]), "=r"(bfr[2 * p][1]),
                           "=r"(bfr[2 * p + 1][0]), "=r"(bfr[2 * p + 1][1])
                         : "r"(addr));
        }
#pragma unroll
        for (int mi = 0; mi < 2; mi++)
#pragma unroll
            for (int ni = 0; ni < 4; ni++) {
                asm volatile(
                    "mma.sync.aligned.m16n8k16.row.col.f32.f16.f16.f32 "
                    "{%0,%1,%2,%3}, {%4,%5,%6,%7}, {%8,%9}, {%0,%1,%2,%3};"
                    : "+f"(acc[mi][ni][0]), "+f"(acc[mi][ni][1]),
                      "+f"(acc[mi][ni][2]), "+f"(acc[mi][ni][3])
                    : "r"(a[mi][0]), "r"(a[mi][1]), "r"(a[mi][2]), "r"(a[mi][3]),
                      "r"(bfr[ni][0]), "r"(bfr[ni][1]));
            }
        st = (st == NSTG - 1) ? 0 : st + 1;
        stp = (stp == NSTG - 1) ? 0 : stp + 1;
    }

    const int rin = lane >> 2;
    const int cin = (lane & 3) * 2;
    float* hp = g_hp + (size_t)ks * B * NPW;
#pragma unroll
    for (int mi = 0; mi < 2; mi++) {
#pragma unroll
        for (int ni = 0; ni < 4; ni++) {
            int m = m0 + wm * 32 + mi * 16 + rin;
            int n = n0 + wn * 32 + ni * 8 + cin;
            float2 v0 = make_float2(acc[mi][ni][0], acc[mi][ni][1]);
            float2 v1 = make_float2(acc[mi][ni][2], acc[mi][ni][3]);
            *(float2*)(hp + (size_t)m * NPW + n)       = v0;
            *(float2*)(hp + (size_t)(m + 8) * NPW + n) = v1;
        }
    }
#undef LOAD_C
}

// ---------------------------------------------------------------------------
// Kernel C2: reduce split-K, + b_fc, bn2, relu -> g_hb (fp16, K padded)
// ---------------------------------------------------------------------------
__global__ void kC2(const float* __restrict__ b_fc,
                    const float* __restrict__ g2, const float* __restrict__ b2,
                    const float* __restrict__ m2, const float* __restrict__ v2) {
    int i = blockIdx.x * blockDim.x + threadIdx.x;
    if (i >= B * KP) return;
    int b = i / KP;
    int d = i % KP;
    if (d >= D) { g_hb[i] = __float2half(0.f); return; }
    float s = 0.f;
#pragma unroll
    for (int ks = 0; ks < KSPLIT; ks++)
        s += g_hp[(size_t)ks * B * NPW + (size_t)b * NPW + d];
    s += b_fc[d];
    float sc = g2[d] / sqrtf(v2[d] + EPSV);
    s = (s - m2[d]) * sc + b2[d];
    g_hb[i] = __float2half(fmaxf(s, 0.f));
}

// ---------------------------------------------------------------------------
// Kernel D: out[m,n] = sigmoid( h[m,:] . E[n,:] + bias[n] )
// FP16 mma, F32 acc. K=208 smem layout; math over K=200 exactly:
// 6 chunks of 32 (12 k16 ksubs) + tail chunk: ONE m16n8k8 (k=192..200).
// BM=64 x BN=256; 3-stage cp.async ring; 256 thr (2x4 warps; 32x64/warp).
// grid = (B/BM, NPAD/BN)
// ---------------------------------------------------------------------------
__global__ void __launch_bounds__(256, 2)
kD(const float* __restrict__ bias, float* __restrict__ out) {
    extern __shared__ __align__(16) __half dsm[];
    __half* Asm = dsm;                       // [NSTG][BM][40]
    __half* Bsm = dsm + NSTG * BM * 40;      // [NSTG][BN][40]

    const int m0 = blockIdx.x * BM;
    const int n0 = blockIdx.y * BN;
    const int tid = threadIdx.x;
    const int lane = tid & 31;
    const int wid = tid >> 5;
    const int wm = wid >> 2;    // 0..1  -> m offset 32
    const int wn = wid & 3;     // 0..3  -> n offset 64

    float acc[2][8][4];
#pragma unroll
    for (int i = 0; i < 2; i++)
#pragma unroll
        for (int j = 0; j < 8; j++)
#pragma unroll
            for (int c = 0; c < 4; c++) acc[i][j][c] = 0.f;

    const int ar = tid >> 2, ac = (tid & 3) * 8;

#define LOAD_D(S, KS, KSZ)                                                         \
    do {                                                                           \
        if (ac < (KSZ)) {                                                          \
            unsigned dst = (unsigned)__cvta_generic_to_shared(                     \
                &Asm[((S) * BM + ar) * 40 + ac]);                                  \
            const __half* src = &g_hb[(size_t)(m0 + ar) * KP + (KS) + ac];         \
            asm volatile("cp.async.cg.shared.global [%0], [%1], 16;\n"             \
                         :: "r"(dst), "l"(src));                                   \
        }                                                                          \
        _Pragma("unroll")                                                          \
        for (int h = 0; h < 4; h++) {                                              \
            int ch = tid + h * 256;                                                \
            int br = ch >> 2, bc = (ch & 3) * 8;                                   \
            if (bc < (KSZ)) {                                                      \
                unsigned dst = (unsigned)__cvta_generic_to_shared(                 \
                    &Bsm[((S) * BN + br) * 40 + bc]);                              \
                const __half* src = &g_Eb[(size_t)(n0 + br) * KP + (KS) + bc];     \
                asm volatile("cp.async.cg.shared.global [%0], [%1], 16;\n"         \
                             :: "r"(dst), "l"(src));                               \
            }                                                                      \
        }                                                                          \
        asm volatile("cp.async.commit_group;\n" ::);                               \
    } while (0)

    LOAD_D(0, 0, 32);
    LOAD_D(1, 32, 32);

    int st = 0;
    int stp = 2;
#pragma unroll
    for (int s = 0; s < NK; s++) {
        asm volatile("cp.async.wait_group 1;\n" ::);
        __syncthreads();

        if (s + 2 < NK) {
            LOAD_D(stp, (s + 2) * 32, (s + 2 == NK - 1) ? 16 : 32);
        } else {
            asm volatile("cp.async.commit_group;\n" ::);
        }

        if (s < NK - 1) {
            // full chunk: two k16 ksubs
#pragma unroll
            for (int ksub = 0; ksub < 2; ksub++) {
                unsigned a[2][4];
                unsigned bfr[8][2];
#pragma unroll
                for (int mi = 0; mi < 2; mi++) {
                    unsigned addr = (unsigned)__cvta_generic_to_shared(
                        &Asm[(st * BM + wm * 32 + mi * 16 + (lane & 15)) * 40
                             + ksub * 16 + (lane >> 4) * 8]);
                    asm volatile("ldmatrix.sync.aligned.m8n8.x4.shared.b16 {%0,%1,%2,%3}, [%4];"
                                 : "=r"(a[mi][0]), "=r"(a[mi][1]), "=r"(a[mi][2]), "=r"(a[mi][3])
                                 : "r"(addr));
                }
#pragma unroll
                for (int p = 0; p < 4; p++) {
                    unsigned addr = (unsigned)__cvta_generic_to_shared(
                        &Bsm[(st * BN + wn * 64 + p * 16 + ((lane >> 4) << 3) + (lane & 7)) * 40
                             + ksub * 16 + ((lane >> 3) & 1) * 8]);
                    asm volatile("ldmatrix.sync.aligned.m8n8.x4.shared.b16 {%0,%1,%2,%3}, [%4];"
                                 : "=r"(bfr[2 * p][0]), "=r"(bfr[2 * p][1]),
                                   "=r"(bfr[2 * p + 1][0]), "=r"(bfr[2 * p + 1][1])
                                 : "r"(addr));
                }
#pragma unroll
                for (int mi = 0; mi < 2; mi++)
#pragma unroll
                    for (int ni = 0; ni < 8; ni++) {
                        asm volatile(
                            "mma.sync.aligned.m16n8k16.row.col.f32.f16.f16.f32 "
                            "{%0,%1,%2,%3}, {%4,%5,%6,%7}, {%8,%9}, {%0,%1,%2,%3};"
                            : "+f"(acc[mi][ni][0]), "+f"(acc[mi][ni][1]),
                              "+f"(acc[mi][ni][2]), "+f"(acc[mi][ni][3])
                            : "r"(a[mi][0]), "r"(a[mi][1]), "r"(a[mi][2]), "r"(a[mi][3]),
                              "r"(bfr[ni][0]), "r"(bfr[ni][1]));
                    }
            }
        } else {
            // tail chunk: k = 192..200 real; single m16n8k8 on fragment halves.
            unsigned a[2][4];
            unsigned bfr[8][2];
#pragma unroll
            for (int mi = 0; mi < 2; mi++) {
                unsigned addr = (unsigned)__cvta_generic_to_shared(
                    &Asm[(st * BM + wm * 32 + mi * 16 + (lane & 15)) * 40
                         + (lane >> 4) * 8]);
                asm volatile("ldmatrix.sync.aligned.m8n8.x4.shared.b16 {%0,%1,%2,%3}, [%4];"
                             : "=r"(a[mi][0]), "=r"(a[mi][1]), "=r"(a[mi][2]), "=r"(a[mi][3])
                             : "r"(addr));
            }
#pragma unroll
            for (int p = 0; p < 4; p++) {
                unsigned addr = (unsigned)__cvta_generic_to_shared(
                    &Bsm[(st * BN + wn * 64 + p * 16 + ((lane >> 4) << 3) + (lane & 7)) * 40
                         + ((lane >> 3) & 1) * 8]);
                asm volatile("ldmatrix.sync.aligned.m8n8.x4.shared.b16 {%0,%1,%2,%3}, [%4];"
                             : "=r"(bfr[2 * p][0]), "=r"(bfr[2 * p][1]),
                               "=r"(bfr[2 * p + 1][0]), "=r"(bfr[2 * p + 1][1])
                             : "r"(addr));
            }
#pragma unroll
            for (int mi = 0; mi < 2; mi++)
#pragma unroll
                for (int ni = 0; ni < 8; ni++) {
                    asm volatile(
                        "mma.sync.aligned.m16n8k8.row.col.f32.f16.f16.f32 "
                        "{%0,%1,%2,%3}, {%4,%5}, {%6}, {%0,%1,%2,%3};"
                        : "+f"(acc[mi][ni][0]), "+f"(acc[mi][ni][1]),
                          "+f"(acc[mi][ni][2]), "+f"(acc[mi][ni][3])
                        : "r"(a[mi][0]), "r"(a[mi][1]),
                          "r"(bfr[ni][0]));
                }
        }
        st = (st == NSTG - 1) ? 0 : st + 1;
        stp = (stp == NSTG - 1) ? 0 : stp + 1;
    }

    // epilogue: bias + sigmoid (fast reciprocal), float2 stores
    const int rin = lane >> 2;
    const int cin = (lane & 3) * 2;
#pragma unroll
    for (int ni = 0; ni < 8; ni++) {
        int n = n0 + wn * 64 + ni * 8 + cin;
        if (n >= NNE) continue;
        float2 bz = *(const float2*)(bias + n);
#pragma unroll
        for (int mi = 0; mi < 2; mi++) {
            int m = m0 + wm * 32 + mi * 16 + rin;
            float2 o0, o1;
            o0.x = __fdividef(1.f, 1.f + __expf(-(acc[mi][ni][0] + bz.x)));
            o0.y = __fdividef(1.f, 1.f + __expf(-(acc[mi][ni][1] + bz.y)));
            o1.x = __fdividef(1.f, 1.f + __expf(-(acc[mi][ni][2] + bz.x)));
            o1.y = __fdividef(1.f, 1.f + __expf(-(acc[mi][ni][3] + bz.y)));
            *(float2*)(out + (size_t)m * NNE + n)       = o0;
            *(float2*)(out + (size_t)(m + 8) * NNE + n) = o1;
        }
    }
#undef LOAD_D
}

// ---------------------------------------------------------------------------
extern "C" void kernel_launch(void* const* d_in, const int* in_sizes, int n_in,
                              void* d_out, int out_size) {
    const int*   e1_idx = (const int*)d_in[0];
    const int*   r_idx  = (const int*)d_in[1];
    const float* E      = (const float*)d_in[2];
    const float* R      = (const float*)d_in[3];
    const float* W_fc   = (const float*)d_in[4];
    const float* b_fc   = (const float*)d_in[5];
    const float* W_fc1  = (const float*)d_in[6];
    const float* b_fc1  = (const float*)d_in[7];
    const float* bn0_g  = (const float*)d_in[8];
    const float* bn0_b  = (const float*)d_in[9];
    const float* bn0_m  = (const float*)d_in[10];
    const float* bn0_v  = (const float*)d_in[11];
    const float* bn1_g  = (const float*)d_in[12];
    const float* bn1_b  = (const float*)d_in[13];
    const float* bn1_m  = (const float*)d_in[14];
    const float* bn1_v  = (const float*)d_in[15];
    const float* bn2_g  = (const float*)d_in[16];
    const float* bn2_b  = (const float*)d_in[17];
    const float* bn2_m  = (const float*)d_in[18];
    const float* bn2_v  = (const float*)d_in[19];
    const float* bvec   = (const float*)d_in[20];
    float* out = (float*)d_out;

    static int init_done = 0;
    static cudaStream_t s1;
    static cudaEvent_t evFork, evW, evE;
    if (!init_done) {
        cudaFuncSetAttribute(kD, cudaFuncAttributeMaxDynamicSharedMemorySize, KD_SMEM);
        cudaStreamCreateWithFlags(&s1, cudaStreamNonBlocking);
        cudaEventCreateWithFlags(&evFork, cudaEventDisableTiming);
        cudaEventCreateWithFlags(&evW, cudaEventDisableTiming);
        cudaEventCreateWithFlags(&evE, cudaEventDisableTiming);
        init_done = 1;
    }

    // Round-14 DAG (measured best):
    //   s0: kAB ---(wait evW)--> kC1m -> kC2 --(wait evE)--> kD
    //   s1: convW -evW-> convE -evE
    cudaEventRecord(evFork, 0);
    cudaStreamWaitEvent(s1, evFork, 0);
    convW<<<(int)(((size_t)NPW * KTOT + 255) / 256), 256, 0, s1>>>(W_fc);
    cudaEventRecord(evW, s1);
    convE<<<(int)(((size_t)NPAD * KP + 255) / 256), 256, 0, s1>>>(E);
    cudaEventRecord(evE, s1);

    kAB<<<B / 8, KFW>>>(e1_idx, r_idx, E, R, W_fc1, b_fc1,
                        bn0_g, bn0_b, bn0_m, bn0_v, bn1_g, bn1_b, bn1_m, bn1_v);
    cudaStreamWaitEvent(0, evW, 0);
    kC1m<<<dim3(B / C_BM, NPW / C_BN, KSPLIT), 256>>>();
    kC2<<<(B * KP + 255) / 256, 256>>>(b_fc, bn2_g, bn2_b, bn2_m, bn2_v);

    cudaStreamWaitEvent(0, evE, 0);
    dim3 gD(B / BM, NPAD / BN);
    kD<<<gD, 256, KD_SMEM>>>(bvec, out);
}

// round 17
// speedup vs baseline: 1.3318x; 1.0142x over previous
#include <cuda_runtime.h>
#include <cuda_fp16.h>
#include <cstdint>
#include <math.h>

#define B 1024
#define NNE 100000
#define NPAD 100096          // padded rows of E (multiple of 256)
#define D 200
#define KP 208               // K padded: 6 chunks of 32 + 1 chunk of 16
#define OC 32
#define FW 9
#define LL 192               // D - FW + 1
#define KTOT (OC * LL)       // 6144
#define KFW (OC * FW)        // 288
#define KSPLIT 8
#define NPW 256              // padded output cols of kC1m
#define EPSV 1e-5f

// kD tiling
#define BM 64
#define BN 256
#define NK 7                 // 6 full chunks (32) + 1 tail chunk (16)
#define NSTG 3
#define KD_SMEM (NSTG * (BM + BN) * 40 * 2)   // 76800 B

// kC1m tiling
#define C_BM 64
#define C_BN 128
#define C_STEPS (KTOT / KSPLIT / 16)   // 48

// scratch (no allocations allowed)
__device__ __half g_yb[B * KTOT];
__device__ __half g_Wb[(size_t)NPW * KTOT];
__device__ float g_hp[(size_t)KSPLIT * B * NPW];
__device__ __half g_hb[B * KP];
__device__ __half g_Eb[(size_t)NPAD * KP];

// ---------------------------------------------------------------------------
// convE: E (fp32, NNE x D) -> g_Eb (fp16, NPAD x KP) zero-padded
// ---------------------------------------------------------------------------
__global__ void convE(const float* __restrict__ E) {
    size_t i = (size_t)blockIdx.x * blockDim.x + threadIdx.x;
    if (i >= (size_t)NPAD * KP) return;
    int n = (int)(i / KP);
    int k = (int)(i % KP);
    float v = (n < NNE && k < D) ? E[(size_t)n * D + k] : 0.f;
    g_Eb[i] = __float2half(v);
}

// ---------------------------------------------------------------------------
// convW: W_fc (fp32, KTOT x D) -> g_Wb (fp16, NPW x KTOT) transposed, padded
// ---------------------------------------------------------------------------
__global__ void convW(const float* __restrict__ W_fc) {
    size_t i = (size_t)blockIdx.x * blockDim.x + threadIdx.x;
    if (i >= (size_t)NPW * KTOT) return;
    int k = (int)(i / NPW);
    int n = (int)(i % NPW);
    float v = (n < D) ? W_fc[(size_t)k * D + n] : 0.f;
    g_Wb[(size_t)n * KTOT + k] = __float2half(v);
}

// ---------------------------------------------------------------------------
// kAB (fused, batched x8): x = bn0(E[e1]); k = R[r] @ W_fc1 + b_fc1;
//   y[b,o,l] = bn1(sum_w x[b,l+w]*k[b,o,w]) -> g_yb (fp16)
// grid = B/8, block = 288. d-loop unrolled x8 for MLP on W_fc1 L2 hits.
// ---------------------------------------------------------------------------
__global__ void kAB(const int* __restrict__ e1_idx, const int* __restrict__ r_idx,
                    const float* __restrict__ E, const float* __restrict__ R,
                    const float* __restrict__ W_fc1, const float* __restrict__ b_fc1,
                    const float* __restrict__ pg0, const float* __restrict__ pb0,
                    const float* __restrict__ pm0, const float* __restrict__ pv0,
                    const float* __restrict__ g1, const float* __restrict__ b1,
                    const float* __restrict__ m1, const float* __restrict__ v1) {
    int bbase = blockIdx.x * 8;
    int t = threadIdx.x;
    __shared__ float rs[8][D];
    __shared__ float xs[8][D];
    __shared__ float kb[8][KFW];
    float s0 = pg0[0] / sqrtf(pv0[0] + EPSV);
    float bb0 = pb0[0], mm0 = pm0[0];
    for (int i = t; i < 8 * D; i += KFW) {
        int g = i / D, d = i % D;
        int bi = bbase + g;
        rs[g][d] = R[(size_t)r_idx[bi] * D + d];
        xs[g][d] = (E[(size_t)e1_idx[bi] * D + d] - mm0) * s0 + bb0;
    }
    __syncthreads();
    {
        float acc[8];
#pragma unroll
        for (int g = 0; g < 8; g++) acc[g] = b_fc1[t];
        // D = 200 = 8 * 25; batch 8 independent LDGs per iteration (MLP=8)
        for (int d = 0; d < D; d += 8) {
            float w[8];
#pragma unroll
            for (int j = 0; j < 8; j++)
                w[j] = W_fc1[(d + j) * KFW + t];
#pragma unroll
            for (int j = 0; j < 8; j++) {
                float ww = w[j];
#pragma unroll
                for (int g = 0; g < 8; g++)
                    acc[g] += rs[g][d + j] * ww;
            }
        }
#pragma unroll
        for (int g = 0; g < 8; g++) kb[g][t] = acc[g];
    }
    __syncthreads();
    if (t < LL) {
        int l = t;
        for (int o = 0; o < OC; o++) {
            float s = g1[o] / sqrtf(v1[o] + EPSV);
            float mo = m1[o], bo = b1[o];
#pragma unroll
            for (int g = 0; g < 8; g++) {
                float acc = 0.f;
#pragma unroll
                for (int w = 0; w < FW; w++) acc += xs[g][l + w] * kb[g][o * FW + w];
                g_yb[(bbase + g) * KTOT + o * LL + l] = __float2half((acc - mo) * s + bo);
            }
        }
    }
}

// ---------------------------------------------------------------------------
// Kernel C1m: partial h = Y(1024x6144,fp16) @ Wb^T (NPWx6144,fp16), split-K=8
// ---------------------------------------------------------------------------
__global__ void __launch_bounds__(256)
kC1m() {
    __shared__ __align__(16) __half As[NSTG][C_BM][24];
    __shared__ __align__(16) __half Bs[NSTG][C_BN][24];

    const int m0 = blockIdx.x * C_BM;
    const int n0 = blockIdx.y * C_BN;
    const int ks = blockIdx.z;
    const int k0 = ks * (KTOT / KSPLIT);
    const int tid = threadIdx.x;
    const int lane = tid & 31;
    const int wid = tid >> 5;
    const int wm = wid >> 2;
    const int wn = wid & 3;

    float acc[2][4][4];
#pragma unroll
    for (int i = 0; i < 2; i++)
#pragma unroll
        for (int j = 0; j < 4; j++)
#pragma unroll
            for (int c = 0; c < 4; c++) acc[i][j][c] = 0.f;

    const int arow = tid >> 1, ac8 = (tid & 1) * 8;

#define LOAD_C(S, KS)                                                            \
    do {                                                                         \
        if (tid < 128) {                                                         \
            unsigned dst = (unsigned)__cvta_generic_to_shared(&As[S][arow][ac8]);\
            const __half* src = &g_yb[(size_t)(m0 + arow) * KTOT + k0 + (KS) + ac8];\
            asm volatile("cp.async.cg.shared.global [%0], [%1], 16;\n"           \
                         :: "r"(dst), "l"(src));                                 \
        }                                                                        \
        {                                                                        \
            unsigned dst = (unsigned)__cvta_generic_to_shared(&Bs[S][arow][ac8]);\
            const __half* src = &g_Wb[(size_t)(n0 + arow) * KTOT + k0 + (KS) + ac8];\
            asm volatile("cp.async.cg.shared.global [%0], [%1], 16;\n"           \
                         :: "r"(dst), "l"(src));                                 \
        }                                                                        \
        asm volatile("cp.async.commit_group;\n" ::);                             \
    } while (0)

    LOAD_C(0, 0);
    LOAD_C(1, 16);

    int st = 0;
    int stp = 2;
    for (int s = 0; s < C_STEPS; s++) {
        asm volatile("cp.async.wait_group 1;\n" ::);
        __syncthreads();

        if (s + 2 < C_STEPS) {
            LOAD_C(stp, (s + 2) * 16);
        } else {
            asm volatile("cp.async.commit_group;\n" ::);
        }

        unsigned a[2][4];
        unsigned bfr[4][2];
#pragma unroll
        for (int mi = 0; mi < 2; mi++) {
            unsigned addr = (unsigned)__cvta_generic_to_shared(
                &As[st][wm * 32 + mi * 16 + (lane & 15)][(lane >> 4) * 8]);
            asm volatile("ldmatrix.sync.aligned.m8n8.x4.shared.b16 {%0,%1,%2,%3}, [%4];"
                         : "=r"(a[mi][0]), "=r"(a[mi][1]), "=r"(a[mi][2]), "=r"(a[mi][3])
                         : "r"(addr));
        }
#pragma unroll
        for (int p = 0; p < 2; p++) {
            unsigned addr = (unsigned)__cvta_generic_to_shared(
                &Bs[st][wn * 32 + p * 16 + ((lane >> 4) << 3) + (lane & 7)]
                   [((lane >> 3) & 1) * 8]);
            asm volatile("ldmatrix.sync.aligned.m8n8.x4.shared.b16 {%0,%1,%2,%3}, [%4];"
                         : "=r"(bfr[2 * p][0]), "=r"(bfr[2 * p][1]),
                           "=r"(bfr[2 * p + 1][0]), "=r"(bfr[2 * p + 1][1])
                         : "r"(addr));
        }
#pragma unroll
        for (int mi = 0; mi < 2; mi++)
#pragma unroll
            for (int ni = 0; ni < 4; ni++) {
                asm volatile(
                    "mma.sync.aligned.m16n8k16.row.col.f32.f16.f16.f32 "
                    "{%0,%1,%2,%3}, {%4,%5,%6,%7}, {%8,%9}, {%0,%1,%2,%3};"
                    : "+f"(acc[mi][ni][0]), "+f"(acc[mi][ni][1]),
                      "+f"(acc[mi][ni][2]), "+f"(acc[mi][ni][3])
                    : "r"(a[mi][0]), "r"(a[mi][1]), "r"(a[mi][2]), "r"(a[mi][3]),
                      "r"(bfr[ni][0]), "r"(bfr[ni][1]));
            }
        st = (st == NSTG - 1) ? 0 : st + 1;
        stp = (stp == NSTG - 1) ? 0 : stp + 1;
    }

    const int rin = lane >> 2;
    const int cin = (lane & 3) * 2;
    float* hp = g_hp + (size_t)ks * B * NPW;
#pragma unroll
    for (int mi = 0; mi < 2; mi++) {
#pragma unroll
        for (int ni = 0; ni < 4; ni++) {
            int m = m0 + wm * 32 + mi * 16 + rin;
            int n = n0 + wn * 32 + ni * 8 + cin;
            float2 v0 = make_float2(acc[mi][ni][0], acc[mi][ni][1]);
            float2 v1 = make_float2(acc[mi][ni][2], acc[mi][ni][3]);
            *(float2*)(hp + (size_t)m * NPW + n)       = v0;
            *(float2*)(hp + (size_t)(m + 8) * NPW + n) = v1;
        }
    }
#undef LOAD_C
}

// ---------------------------------------------------------------------------
// Kernel C2: reduce split-K, + b_fc, bn2, relu -> g_hb (fp16, K padded)
// ---------------------------------------------------------------------------
__global__ void kC2(const float* __restrict__ b_fc,
                    const float* __restrict__ g2, const float* __restrict__ b2,
                    const float* __restrict__ m2, const float* __restrict__ v2) {
    int i = blockIdx.x * blockDim.x + threadIdx.x;
    if (i >= B * KP) return;
    int b = i / KP;
    int d = i % KP;
    if (d >= D) { g_hb[i] = __float2half(0.f); return; }
    float s = 0.f;
#pragma unroll
    for (int ks = 0; ks < KSPLIT; ks++)
        s += g_hp[(size_t)ks * B * NPW + (size_t)b * NPW + d];
    s += b_fc[d];
    float sc = g2[d] / sqrtf(v2[d] + EPSV);
    s = (s - m2[d]) * sc + b2[d];
    g_hb[i] = __float2half(fmaxf(s, 0.f));
}

// ---------------------------------------------------------------------------
// Kernel D: out[m,n] = sigmoid( h[m,:] . E[n,:] + bias[n] )
// FP16 mma, F32 acc. K=208 smem layout; math over K=200 exactly:
// 6 chunks of 32 (12 k16 ksubs) + tail chunk: ONE m16n8k8 (k=192..200).
// BM=64 x BN=256; 3-stage cp.async ring; 256 thr (2x4 warps; 32x64/warp).
// grid = (B/BM, NPAD/BN)
// ---------------------------------------------------------------------------
__global__ void __launch_bounds__(256, 2)
kD(const float* __restrict__ bias, float* __restrict__ out) {
    extern __shared__ __align__(16) __half dsm[];
    __half* Asm = dsm;                       // [NSTG][BM][40]
    __half* Bsm = dsm + NSTG * BM * 40;      // [NSTG][BN][40]

    const int m0 = blockIdx.x * BM;
    const int n0 = blockIdx.y * BN;
    const int tid = threadIdx.x;
    const int lane = tid & 31;
    const int wid = tid >> 5;
    const int wm = wid >> 2;    // 0..1  -> m offset 32
    const int wn = wid & 3;     // 0..3  -> n offset 64

    float acc[2][8][4];
#pragma unroll
    for (int i = 0; i < 2; i++)
#pragma unroll
        for (int j = 0; j < 8; j++)
#pragma unroll
            for (int c = 0; c < 4; c++) acc[i][j][c] = 0.f;

    const int ar = tid >> 2, ac = (tid & 3) * 8;

#define LOAD_D(S, KS, KSZ)                                                         \
    do {                                                                           \
        if (ac < (KSZ)) {                                                          \
            unsigned dst = (unsigned)__cvta_generic_to_shared(                     \
                &Asm[((S) * BM + ar) * 40 + ac]);                                  \
            const __half* src = &g_hb[(size_t)(m0 + ar) * KP + (KS) + ac];         \
            asm volatile("cp.async.cg.shared.global [%0], [%1], 16;\n"             \
                         :: "r"(dst), "l"(src));                                   \
        }                                                                          \
        _Pragma("unroll")                                                          \
        for (int h = 0; h < 4; h++) {                                              \
            int ch = tid + h * 256;                                                \
            int br = ch >> 2, bc = (ch & 3) * 8;                                   \
            if (bc < (KSZ)) {                                                      \
                unsigned dst = (unsigned)__cvta_generic_to_shared(                 \
                    &Bsm[((S) * BN + br) * 40 + bc]);                              \
                const __half* src = &g_Eb[(size_t)(n0 + br) * KP + (KS) + bc];     \
                asm volatile("cp.async.cg.shared.global [%0], [%1], 16;\n"         \
                             :: "r"(dst), "l"(src));                               \
            }                                                                      \
        }                                                                          \
        asm volatile("cp.async.commit_group;\n" ::);                               \
    } while (0)

    LOAD_D(0, 0, 32);
    LOAD_D(1, 32, 32);

    int st = 0;
    int stp = 2;
#pragma unroll
    for (int s = 0; s < NK; s++) {
        asm volatile("cp.async.wait_group 1;\n" ::);
        __syncthreads();

        if (s + 2 < NK) {
            LOAD_D(stp, (s + 2) * 32, (s + 2 == NK - 1) ? 16 : 32);
        } else {
            asm volatile("cp.async.commit_group;\n" ::);
        }

        if (s < NK - 1) {
            // full chunk: two k16 ksubs
#pragma unroll
            for (int ksub = 0; ksub < 2; ksub++) {
                unsigned a[2][4];
                unsigned bfr[8][2];
#pragma unroll
                for (int mi = 0; mi < 2; mi++) {
                    unsigned addr = (unsigned)__cvta_generic_to_shared(
                        &Asm[(st * BM + wm * 32 + mi * 16 + (lane & 15)) * 40
                             + ksub * 16 + (lane >> 4) * 8]);
                    asm volatile("ldmatrix.sync.aligned.m8n8.x4.shared.b16 {%0,%1,%2,%3}, [%4];"
                                 : "=r"(a[mi][0]), "=r"(a[mi][1]), "=r"(a[mi][2]), "=r"(a[mi][3])
                                 : "r"(addr));
                }
#pragma unroll
                for (int p = 0; p < 4; p++) {
                    unsigned addr = (unsigned)__cvta_generic_to_shared(
                        &Bsm[(st * BN + wn * 64 + p * 16 + ((lane >> 4) << 3) + (lane & 7)) * 40
                             + ksub * 16 + ((lane >> 3) & 1) * 8]);
                    asm volatile("ldmatrix.sync.aligned.m8n8.x4.shared.b16 {%0,%1,%2,%3}, [%4];"
                                 : "=r"(bfr[2 * p][0]), "=r"(bfr[2 * p][1]),
                                   "=r"(bfr[2 * p + 1][0]), "=r"(bfr[2 * p + 1][1])
                                 : "r"(addr));
                }
#pragma unroll
                for (int mi = 0; mi < 2; mi++)
#pragma unroll
                    for (int ni = 0; ni < 8; ni++) {
                        asm volatile(
                            "mma.sync.aligned.m16n8k16.row.col.f32.f16.f16.f32 "
                            "{%0,%1,%2,%3}, {%4,%5,%6,%7}, {%8,%9}, {%0,%1,%2,%3};"
                            : "+f"(acc[mi][ni][0]), "+f"(acc[mi][ni][1]),
                              "+f"(acc[mi][ni][2]), "+f"(acc[mi][ni][3])
                            : "r"(a[mi][0]), "r"(a[mi][1]), "r"(a[mi][2]), "r"(a[mi][3]),
                              "r"(bfr[ni][0]), "r"(bfr[ni][1]));
                    }
            }
        } else {
            // tail chunk: k = 192..200 real; single m16n8k8 on fragment halves.
            unsigned a[2][4];
            unsigned bfr[8][2];
#pragma unroll
            for (int mi = 0; mi < 2; mi++) {
                unsigned addr = (unsigned)__cvta_generic_to_shared(
                    &Asm[(st * BM + wm * 32 + mi * 16 + (lane & 15)) * 40
                         + (lane >> 4) * 8]);
                asm volatile("ldmatrix.sync.aligned.m8n8.x4.shared.b16 {%0,%1,%2,%3}, [%4];"
                             : "=r"(a[mi][0]), "=r"(a[mi][1]), "=r"(a[mi][2]), "=r"(a[mi][3])
                             : "r"(addr));
            }
#pragma unroll
            for (int p = 0; p < 4; p++) {
                unsigned addr = (unsigned)__cvta_generic_to_shared(
                    &Bsm[(st * BN + wn * 64 + p * 16 + ((lane >> 4) << 3) + (lane & 7)) * 40
                         + ((lane >> 3) & 1) * 8]);
                asm volatile("ldmatrix.sync.aligned.m8n8.x4.shared.b16 {%0,%1,%2,%3}, [%4];"
                             : "=r"(bfr[2 * p][0]), "=r"(bfr[2 * p][1]),
                               "=r"(bfr[2 * p + 1][0]), "=r"(bfr[2 * p + 1][1])
                             : "r"(addr));
            }
#pragma unroll
            for (int mi = 0; mi < 2; mi++)
#pragma unroll
                for (int ni = 0; ni < 8; ni++) {
                    asm volatile(
                        "mma.sync.aligned.m16n8k8.row.col.f32.f16.f16.f32 "
                        "{%0,%1,%2,%3}, {%4,%5}, {%6}, {%0,%1,%2,%3};"
                        : "+f"(acc[mi][ni][0]), "+f"(acc[mi][ni][1]),
                          "+f"(acc[mi][ni][2]), "+f"(acc[mi][ni][3])
                        : "r"(a[mi][0]), "r"(a[mi][1]),
                          "r"(bfr[ni][0]));
                }
        }
        st = (st == NSTG - 1) ? 0 : st + 1;
        stp = (stp == NSTG - 1) ? 0 : stp + 1;
    }

    // epilogue: bias + sigmoid (fast reciprocal), float2 stores
    const int rin = lane >> 2;
    const int cin = (lane & 3) * 2;
#pragma unroll
    for (int ni = 0; ni < 8; ni++) {
        int n = n0 + wn * 64 + ni * 8 + cin;
        if (n >= NNE) continue;
        float2 bz = *(const float2*)(bias + n);
#pragma unroll
        for (int mi = 0; mi < 2; mi++) {
            int m = m0 + wm * 32 + mi * 16 + rin;
            float2 o0, o1;
            o0.x = __fdividef(1.f, 1.f + __expf(-(acc[mi][ni][0] + bz.x)));
            o0.y = __fdividef(1.f, 1.f + __expf(-(acc[mi][ni][1] + bz.y)));
            o1.x = __fdividef(1.f, 1.f + __expf(-(acc[mi][ni][2] + bz.x)));
            o1.y = __fdividef(1.f, 1.f + __expf(-(acc[mi][ni][3] + bz.y)));
            *(float2*)(out + (size_t)m * NNE + n)       = o0;
            *(float2*)(out + (size_t)(m + 8) * NNE + n) = o1;
        }
    }
#undef LOAD_D
}

// ---------------------------------------------------------------------------
extern "C" void kernel_launch(void* const* d_in, const int* in_sizes, int n_in,
                              void* d_out, int out_size) {
    const int*   e1_idx = (const int*)d_in[0];
    const int*   r_idx  = (const int*)d_in[1];
    const float* E      = (const float*)d_in[2];
    const float* R      = (const float*)d_in[3];
    const float* W_fc   = (const float*)d_in[4];
    const float* b_fc   = (const float*)d_in[5];
    const float* W_fc1  = (const float*)d_in[6];
    const float* b_fc1  = (const float*)d_in[7];
    const float* bn0_g  = (const float*)d_in[8];
    const float* bn0_b  = (const float*)d_in[9];
    const float* bn0_m  = (const float*)d_in[10];
    const float* bn0_v  = (const float*)d_in[11];
    const float* bn1_g  = (const float*)d_in[12];
    const float* bn1_b  = (const float*)d_in[13];
    const float* bn1_m  = (const float*)d_in[14];
    const float* bn1_v  = (const float*)d_in[15];
    const float* bn2_g  = (const float*)d_in[16];
    const float* bn2_b  = (const float*)d_in[17];
    const float* bn2_m  = (const float*)d_in[18];
    const float* bn2_v  = (const float*)d_in[19];
    const float* bvec   = (const float*)d_in[20];
    float* out = (float*)d_out;

    static int init_done = 0;
    static cudaStream_t s1;
    static cudaEvent_t evFork, evW, evE;
    if (!init_done) {
        cudaFuncSetAttribute(kD, cudaFuncAttributeMaxDynamicSharedMemorySize, KD_SMEM);
        cudaStreamCreateWithFlags(&s1, cudaStreamNonBlocking);
        cudaEventCreateWithFlags(&evFork, cudaEventDisableTiming);
        cudaEventCreateWithFlags(&evW, cudaEventDisableTiming);
        cudaEventCreateWithFlags(&evE, cudaEventDisableTiming);
        init_done = 1;
    }

    // DAG (round-14 best):
    //   s0: kAB ---(wait evW)--> kC1m -> kC2 --(wait evE)--> kD
    //   s1: convW -evW-> convE -evE
    cudaEventRecord(evFork, 0);
    cudaStreamWaitEvent(s1, evFork, 0);
    convW<<<(int)(((size_t)NPW * KTOT + 255) / 256), 256, 0, s1>>>(W_fc);
    cudaEventRecord(evW, s1);
    convE<<<(int)(((size_t)NPAD * KP + 255) / 256), 256, 0, s1>>>(E);
    cudaEventRecord(evE, s1);

    kAB<<<B / 8, KFW>>>(e1_idx, r_idx, E, R, W_fc1, b_fc1,
                        bn0_g, bn0_b, bn0_m, bn0_v, bn1_g, bn1_b, bn1_m, bn1_v);
    cudaStreamWaitEvent(0, evW, 0);
    kC1m<<<dim3(B / C_BM, NPW / C_BN, KSPLIT), 256>>>();
    kC2<<<(B * KP + 255) / 256, 256>>>(b_fc, bn2_g, bn2_b, bn2_m, bn2_v);

    cudaStreamWaitEvent(0, evE, 0);
    dim3 gD(B / BM, NPAD / BN);
    kD<<<gD, 256, KD_SMEM>>>(bvec, out);
}